// round 15
// baseline (speedup 1.0000x reference)
#include <cuda_runtime.h>
#include <cuda_bf16.h>
#include <cstdint>

#define NROWS 8192
#define DDIM  256
#define TT    64            // CTA tile (64x64)
#define KCH   64            // K chunk in int8 elems = 64 bytes/row
#define NBLK  (NROWS / TT)  // 128
#define NTILES (NBLK * (NBLK + 1) / 2)   // 8256 upper-triangular tiles

// Scratch (no cudaMalloc allowed).
__device__ signed char g_q1[NROWS * DDIM];
__device__ signed char g_q2[NROWS * DDIM];
__device__ float g_tot[NROWS];
__device__ float g_pos[NROWS];

// SMEM per buffer: Aq1 4K | Aq2 4K | Bq1 4K | Bq2 4K = 16KB; 3 buffers = 48KB.
#define BUF_SZ  16384
#define NSTAGE  3
#define DSMEM_TOTAL (NSTAGE * BUF_SZ + 128)

// ---------------------------------------------------------------------------
__device__ __forceinline__ uint32_t smem_u32(const void* p) {
    uint32_t a;
    asm("{ .reg .u64 t; cvta.to.shared.u64 t, %1; cvt.u32.u64 %0, t; }" : "=r"(a) : "l"(p));
    return a;
}
__device__ __forceinline__ void cpa16(uint32_t dst, const void* src) {
    asm volatile("cp.async.cg.shared.global [%0], [%1], 16;" :: "r"(dst), "l"(src));
}
#define CPA_COMMIT() asm volatile("cp.async.commit_group;" ::: "memory")

__device__ __forceinline__ void ldsm4(uint32_t* d, uint32_t addr) {
    asm volatile("ldmatrix.sync.aligned.m8n8.x4.shared.b16 {%0,%1,%2,%3}, [%4];"
                 : "=r"(d[0]), "=r"(d[1]), "=r"(d[2]), "=r"(d[3]) : "r"(addr));
}
// s8 MMA, K=32, s32 accumulate. Fragment layout is the byte-pair isomorphism
// of the (validated) m16n8k16 b16 layout, so ldmatrix addressing is unchanged.
__device__ __forceinline__ void mmas8(int* c, const uint32_t* a, const uint32_t* b) {
    asm volatile("mma.sync.aligned.m16n8k32.row.col.s32.s8.s8.s32 "
                 "{%0,%1,%2,%3}, {%4,%5,%6,%7}, {%8,%9}, {%0,%1,%2,%3};"
                 : "+r"(c[0]), "+r"(c[1]), "+r"(c[2]), "+r"(c[3])
                 : "r"(a[0]), "r"(a[1]), "r"(a[2]), "r"(a[3]), "r"(b[0]), "r"(b[1]));
}

// 64B-row swizzle: unit x = u ^ ((r>>1)&3); (r%2, x) distinct across 8 rows.
__device__ __forceinline__ uint32_t dof64(int r, int u) {
    return (uint32_t)(r * 64 + ((u ^ ((r >> 1) & 3)) << 4));
}

// exp2 on the FMA pipe: float-bias range reduction + degree-5 Taylor on [-0.5,0.5].
__device__ __forceinline__ float fexp2(float s) {
    float z = s + 12582912.0f;
    float f = s - (z - 12582912.0f);
    int   k = __float_as_int(z) << 23;
    float p =             1.3333558e-3f;
    p = fmaf(p, f, 9.6181291e-3f);
    p = fmaf(p, f, 5.5504109e-2f);
    p = fmaf(p, f, 2.4022651e-1f);
    p = fmaf(p, f, 6.9314718e-1f);
    p = fmaf(p, f, 1.0f);
    return __int_as_float(__float_as_int(p) + k);
}

// Fast int->float for |d| < 2^22 (magic-bias add).
__device__ __forceinline__ float smalli2f(int d) {
    return __int_as_float(d + 0x4B400000) - 12582912.0f;
}

// ---------------------------------------------------------------------------
// Kernel 1: normalize rows -> int8 fixed-point pair (q1,q2); zero accumulators.
// y ~= (256*q1 + q2) / 2^14, rounding error <= ~2^-15.
// ---------------------------------------------------------------------------
__global__ void norm_kernel(const float* __restrict__ X) {
    int row  = blockIdx.x * 8 + (threadIdx.x >> 5);
    int lane = threadIdx.x & 31;
    const float4* x4 = reinterpret_cast<const float4*>(X + row * DDIM);
    float4 v1 = x4[lane];
    float4 v2 = x4[lane + 32];
    float ss = v1.x*v1.x + v1.y*v1.y + v1.z*v1.z + v1.w*v1.w
             + v2.x*v2.x + v2.y*v2.y + v2.z*v2.z + v2.w*v2.w;
    #pragma unroll
    for (int o = 16; o > 0; o >>= 1) ss += __shfl_xor_sync(0xffffffffu, ss, o);
    float rinv = rsqrtf(ss);
    float vs[8] = {v1.x*rinv, v1.y*rinv, v1.z*rinv, v1.w*rinv,
                   v2.x*rinv, v2.y*rinv, v2.z*rinv, v2.w*rinv};

    signed char b1[8], b2[8];
    #pragma unroll
    for (int p = 0; p < 8; p++) {
        float y  = vs[p];
        int   i1 = __float2int_rn(y * 64.0f);            // |i1| <= 64
        float r  = y - (float)i1 * 0.015625f;            // exact: i1/64
        int   i2 = __float2int_rn(r * 16384.0f);         // |i2| <= 128
        i2 = max(-127, min(127, i2));
        b1[p] = (signed char)i1;
        b2[p] = (signed char)i2;
    }
    // elements: k = 4*lane + [0..3] and k = 4*(lane+32) + [0..3]
    char4* q1a = reinterpret_cast<char4*>(g_q1 + row * DDIM);
    char4* q2a = reinterpret_cast<char4*>(g_q2 + row * DDIM);
    q1a[lane]      = make_char4(b1[0], b1[1], b1[2], b1[3]);
    q1a[lane + 32] = make_char4(b1[4], b1[5], b1[6], b1[7]);
    q2a[lane]      = make_char4(b2[0], b2[1], b2[2], b2[3]);
    q2a[lane + 32] = make_char4(b2[4], b2[5], b2[6], b2[7]);
    if (lane == 0) { g_tot[row] = 0.0f; g_pos[row] = 0.0f; }
}

// ---------------------------------------------------------------------------
// Kernel 2: int8-split IMMA GEMM on upper-triangular 64x64 tiles, occ 2.
// cos*2^28 = 2^16*D1 + 2^8*D2 + D3 (all exact s32).
// 8 warps as 2(m) x 4(n); warp tile 32x16; 4 MMAs per k32 step.
// ---------------------------------------------------------------------------
__global__ __launch_bounds__(256, 2)
void gemm_imma_kernel(const int* __restrict__ labels, const float* __restrict__ tptr) {
    extern __shared__ char dsm_raw[];
    __shared__ int lr[TT], lcc[TT];

    const int tid  = threadIdx.x;
    const int wid  = tid >> 5;
    const int lane = tid & 31;

    // ---- triangular tile decode: blockIdx.x -> (bi <= bj) ----
    const int k = blockIdx.x;
    int bi = (int)((2.0 * NBLK + 1.0
                    - sqrt((2.0 * NBLK + 1.0) * (2.0 * NBLK + 1.0) - 8.0 * (double)k)) * 0.5);
    while (bi > 0 && bi * NBLK - bi * (bi - 1) / 2 > k) bi--;
    while ((bi + 1) * NBLK - (bi + 1) * bi / 2 <= k) bi++;
    const int bj = bi + (k - (bi * NBLK - bi * (bi - 1) / 2));
    const int row0 = bi * TT;
    const int col0 = bj * TT;
    const bool offdiag = (bi != bj);

    const uint32_t sbase = (smem_u32(dsm_raw) + 127u) & ~127u;

    if (tid < TT)                 lr[tid]       = labels[row0 + tid];
    else if (tid < 2 * TT)        lcc[tid - TT] = labels[col0 + tid - TT];

    const char* q1P = (const char*)g_q1;
    const char* q2P = (const char*)g_q2;

    // per chunk: 4 arrays x 64 rows x 4 units(16B) = 1024 units / 256 thr = 4 each.
    auto load_chunk = [&](int bufidx, int kc) {
        uint32_t b = sbase + bufidx * BUF_SZ;
        #pragma unroll
        for (int i = 0; i < 4; i++) {
            int idx = tid + i * 256;
            int arr = idx >> 8;              // 0:Aq1 1:Aq2 2:Bq1 3:Bq2
            int r   = (idx >> 2) & 63;
            int u   = idx & 3;
            uint32_t dof = dof64(r, u) + arr * 4096;
            int grow = ((arr < 2) ? row0 : col0) + r;
            const char* src = ((arr & 1) ? q2P : q1P)
                            + (size_t)grow * DDIM + kc * KCH + u * 16;
            cpa16(b + dof, src);
        }
    };

    int acc1[2][2][4], acc2[2][2][4], acc3[2][2][4];
    #pragma unroll
    for (int m = 0; m < 2; m++)
        #pragma unroll
        for (int n = 0; n < 2; n++)
            #pragma unroll
            for (int j = 0; j < 4; j++) {
                acc1[m][n][j] = 0; acc2[m][n][j] = 0; acc3[m][n][j] = 0;
            }

    const int wm = wid & 1, wn = wid >> 1;     // 2 x 4 warp grid
    const int sub = lane >> 3, l7 = lane & 7;

    load_chunk(0, 0);
    CPA_COMMIT();
    load_chunk(1, 1);
    CPA_COMMIT();

    const int NCH = DDIM / KCH;  // 4
    int buf = 0;
    #pragma unroll 1
    for (int kc = 0; kc < NCH; kc++) {
        if (kc < NCH - 1) {
            asm volatile("cp.async.wait_group 1;" ::: "memory");
        } else {
            asm volatile("cp.async.wait_group 0;" ::: "memory");
        }
        __syncthreads();

        if (kc + 2 < NCH) {
            load_chunk((buf + 2) % NSTAGE, kc + 2);
            CPA_COMMIT();
        }

        const uint32_t b = sbase + buf * BUF_SZ;
        #pragma unroll
        for (int ks = 0; ks < 2; ks++) {       // two k32 steps per 64B chunk
            uint32_t a1[2][4], a2[2][4], bq1[4], bq2[4];
            #pragma unroll
            for (int ma = 0; ma < 2; ma++) {
                int mr = wm * 32 + ma * 16 + ((sub & 1) << 3) + l7;
                int u  = 2 * ks + (sub >> 1);
                uint32_t dof = dof64(mr, u);
                ldsm4(a1[ma], b + 0    + dof);
                ldsm4(a2[ma], b + 4096 + dof);
            }
            {
                int nr = wn * 16 + ((sub >> 1) << 3) + l7;
                int u  = 2 * ks + (sub & 1);
                uint32_t dof = dof64(nr, u);
                ldsm4(bq1, b + 8192  + dof);
                ldsm4(bq2, b + 12288 + dof);
            }
            #pragma unroll
            for (int ma = 0; ma < 2; ma++)
                #pragma unroll
                for (int nf = 0; nf < 2; nf++) {
                    const uint32_t* B1 = &bq1[nf * 2];
                    const uint32_t* B2 = &bq2[nf * 2];
                    mmas8(acc1[ma][nf], a1[ma], B1);   // q1*q1'
                    mmas8(acc2[ma][nf], a1[ma], B2);   // q1*q2'
                    mmas8(acc2[ma][nf], a2[ma], B1);   // + q2*q1'
                    mmas8(acc3[ma][nf], a2[ma], B2);   // q2*q2'
                }
        }
        buf = (buf + 1) % NSTAGE;
    }
    __syncthreads();

    // ---- Epilogue ----
    const float esc28 = 1.442695041f / (*tptr) * (1.0f / 268435456.0f);  // /2^28
    const int q = lane & 3, g = lane >> 2;

    int cl_[2][2];
    #pragma unroll
    for (int nf = 0; nf < 2; nf++) {
        int cb = wn * 16 + nf * 8 + q * 2;
        cl_[nf][0] = lcc[cb];
        cl_[nf][1] = lcc[cb + 1];
    }

    float ct[2][2], cp[2][2];   // column-side accumulators (off-diag only)
    #pragma unroll
    for (int nf = 0; nf < 2; nf++) { ct[nf][0] = ct[nf][1] = cp[nf][0] = cp[nf][1] = 0.f; }

    #pragma unroll
    for (int ma = 0; ma < 2; ma++) {
        int rA = row0 + wm * 32 + ma * 16 + g;
        int rB = rA + 8;
        int lA = lr[rA - row0], lB = lr[rB - row0];
        float tsA = 0.f, psA = 0.f, tsB = 0.f, psB = 0.f;
        #pragma unroll
        for (int nf = 0; nf < 2; nf++) {
            float e[4];
            #pragma unroll
            for (int j = 0; j < 4; j++) {
                int d23 = acc2[ma][nf][j] * 256 + acc3[ma][nf][j];
                float v = fmaf(smalli2f(acc1[ma][nf][j]), 65536.0f, __int2float_rn(d23));
                e[j] = fexp2(v * esc28);
            }
            bool m0 = (lA == cl_[nf][0]), m1 = (lA == cl_[nf][1]);
            bool m2 = (lB == cl_[nf][0]), m3 = (lB == cl_[nf][1]);
            tsA += e[0] + e[1];
            tsB += e[2] + e[3];
            psA += (m0 ? e[0] : 1.0f) + (m1 ? e[1] : 1.0f);
            psB += (m2 ? e[2] : 1.0f) + (m3 ? e[3] : 1.0f);
            if (offdiag) {
                ct[nf][0] += e[0] + e[2];
                ct[nf][1] += e[1] + e[3];
                cp[nf][0] += (m0 ? e[0] : 1.0f) + (m2 ? e[2] : 1.0f);
                cp[nf][1] += (m1 ? e[1] : 1.0f) + (m3 ? e[3] : 1.0f);
            }
        }
        #pragma unroll
        for (int o = 1; o <= 2; o <<= 1) {
            tsA += __shfl_xor_sync(0xffffffffu, tsA, o);
            psA += __shfl_xor_sync(0xffffffffu, psA, o);
            tsB += __shfl_xor_sync(0xffffffffu, tsB, o);
            psB += __shfl_xor_sync(0xffffffffu, psB, o);
        }
        if (q == 0) {
            atomicAdd(&g_tot[rA], tsA);
            atomicAdd(&g_pos[rA], psA);
            atomicAdd(&g_tot[rB], tsB);
            atomicAdd(&g_pos[rB], psB);
        }
    }

    if (offdiag) {
        #pragma unroll
        for (int nf = 0; nf < 2; nf++)
            #pragma unroll
            for (int bb = 0; bb < 2; bb++) {
                float t = ct[nf][bb], p = cp[nf][bb];
                #pragma unroll
                for (int o = 4; o <= 16; o <<= 1) {
                    t += __shfl_xor_sync(0xffffffffu, t, o);
                    p += __shfl_xor_sync(0xffffffffu, p, o);
                }
                if (g == 0) {
                    int col = col0 + wn * 16 + nf * 8 + q * 2 + bb;
                    atomicAdd(&g_tot[col], t);
                    atomicAdd(&g_pos[col], p);
                }
            }
    }
}

// ---------------------------------------------------------------------------
// Kernel 3: loss = sum_i [log(tot_i + N - pos_i) - log(pos_i)] / N
// ---------------------------------------------------------------------------
__global__ void loss_kernel(float* __restrict__ out) {
    __shared__ double sd[256];
    double a = 0.0;
    for (int r = threadIdx.x; r < NROWS; r += 256) {
        float p  = g_pos[r];
        float ng = g_tot[r] + (float)NROWS - p;
        a += (double)(logf(ng) - logf(p));
    }
    sd[threadIdx.x] = a;
    __syncthreads();
    #pragma unroll
    for (int o = 128; o > 0; o >>= 1) {
        if (threadIdx.x < o) sd[threadIdx.x] += sd[threadIdx.x + o];
        __syncthreads();
    }
    if (threadIdx.x == 0) out[0] = (float)(sd[0] / (double)NROWS);
}

// ---------------------------------------------------------------------------
extern "C" void kernel_launch(void* const* d_in, const int* in_sizes, int n_in,
                              void* d_out, int out_size) {
    const float* X   = (const float*)d_in[0];
    const int*   lab = (const int*)d_in[1];
    const float* t   = (const float*)d_in[2];
    float*       out = (float*)d_out;

    cudaFuncSetAttribute(gemm_imma_kernel, cudaFuncAttributeMaxDynamicSharedMemorySize,
                         DSMEM_TOTAL);

    norm_kernel<<<NROWS / 8, 256>>>(X);
    gemm_imma_kernel<<<NTILES, 256, DSMEM_TOTAL>>>(lab, t);
    loss_kernel<<<1, 256>>>(out);
}

// round 16
// speedup vs baseline: 5.8678x; 5.8678x over previous
#include <cuda_runtime.h>
#include <cuda_bf16.h>
#include <cstdint>

#define NROWS 8192
#define DDIM  256
#define TM    128
#define TN    128
#define KCH   32            // K chunk in bf16 elems = 64 bytes/row
#define NBLK  (NROWS / TM)
#define NTILES (NBLK * (NBLK + 1) / 2)   // 2080 upper-triangular tiles

// Scratch (no cudaMalloc allowed).
__device__ __nv_bfloat16 g_Y[NROWS * DDIM];
__device__ float  g_tot[NROWS];
__device__ float  g_pos[NROWS];
__device__ double g_partial[32];

// SMEM per buffer: A 8K | B 8K = 16KB; 3 buffers = 48KB.
#define OFF_A  0
#define OFF_B  8192
#define BUF_SZ 16384
#define NSTAGE 3
#define DSMEM_TOTAL (NSTAGE * BUF_SZ + 128)

// ---------------------------------------------------------------------------
__device__ __forceinline__ uint32_t smem_u32(const void* p) {
    uint32_t a;
    asm("{ .reg .u64 t; cvta.to.shared.u64 t, %1; cvt.u32.u64 %0, t; }" : "=r"(a) : "l"(p));
    return a;
}
__device__ __forceinline__ void cpa16(uint32_t dst, const void* src) {
    asm volatile("cp.async.cg.shared.global [%0], [%1], 16;" :: "r"(dst), "l"(src));
}
#define CPA_COMMIT() asm volatile("cp.async.commit_group;" ::: "memory")

__device__ __forceinline__ void ldsm4(uint32_t* d, uint32_t addr) {
    asm volatile("ldmatrix.sync.aligned.m8n8.x4.shared.b16 {%0,%1,%2,%3}, [%4];"
                 : "=r"(d[0]), "=r"(d[1]), "=r"(d[2]), "=r"(d[3]) : "r"(addr));
}
__device__ __forceinline__ void mma16816(float* c, const uint32_t* a, const uint32_t* b) {
    asm volatile("mma.sync.aligned.m16n8k16.row.col.f32.bf16.bf16.f32 "
                 "{%0,%1,%2,%3}, {%4,%5,%6,%7}, {%8,%9}, {%0,%1,%2,%3};"
                 : "+f"(c[0]), "+f"(c[1]), "+f"(c[2]), "+f"(c[3])
                 : "r"(a[0]), "r"(a[1]), "r"(a[2]), "r"(a[3]), "r"(b[0]), "r"(b[1]));
}

// 64B-row swizzle: unit x = u ^ ((r>>1)&3); (r%2, x) distinct across 8 rows.
__device__ __forceinline__ uint32_t dof64(int r, int u) {
    return (uint32_t)(r * 64 + ((u ^ ((r >> 1) & 3)) << 4));
}

// exp2 on the FMA pipe: float-bias range reduction + degree-5 Taylor on [-0.5,0.5].
__device__ __forceinline__ float fexp2(float s) {
    float z = s + 12582912.0f;
    float f = s - (z - 12582912.0f);
    int   k = __float_as_int(z) << 23;
    float p =             1.3333558e-3f;
    p = fmaf(p, f, 9.6181291e-3f);
    p = fmaf(p, f, 5.5504109e-2f);
    p = fmaf(p, f, 2.4022651e-1f);
    p = fmaf(p, f, 6.9314718e-1f);
    p = fmaf(p, f, 1.0f);
    return __int_as_float(__float_as_int(p) + k);
}

// ---------------------------------------------------------------------------
// Kernel 1: normalize rows -> bf16; zero accumulators.
// ---------------------------------------------------------------------------
__global__ void norm_kernel(const float* __restrict__ X) {
    int row  = blockIdx.x * 8 + (threadIdx.x >> 5);
    int lane = threadIdx.x & 31;
    const float4* x4 = reinterpret_cast<const float4*>(X + row * DDIM);
    float4 v1 = x4[lane];
    float4 v2 = x4[lane + 32];
    float ss = v1.x*v1.x + v1.y*v1.y + v1.z*v1.z + v1.w*v1.w
             + v2.x*v2.x + v2.y*v2.y + v2.z*v2.z + v2.w*v2.w;
    #pragma unroll
    for (int o = 16; o > 0; o >>= 1) ss += __shfl_xor_sync(0xffffffffu, ss, o);
    float r = rsqrtf(ss);
    float vs[8] = {v1.x*r, v1.y*r, v1.z*r, v1.w*r, v2.x*r, v2.y*r, v2.z*r, v2.w*r};

    __nv_bfloat162* yh = reinterpret_cast<__nv_bfloat162*>(g_Y + row * DDIM);
    #pragma unroll
    for (int p = 0; p < 4; p++) {
        __nv_bfloat162 h = __floats2bfloat162_rn(vs[p * 2], vs[p * 2 + 1]);
        int base = (p < 2) ? (lane * 2 + p) : ((lane + 32) * 2 + (p - 2));
        yh[base] = h;
    }
    if (lane == 0) { g_tot[row] = 0.0f; g_pos[row] = 0.0f; }
}

// ---------------------------------------------------------------------------
// Kernel 2: single-term bf16 HMMA GEMM on upper-triangular tiles, occ 2,
// 3-stage pipeline; exact self-pair patch on diagonal tiles.
// ---------------------------------------------------------------------------
__global__ __launch_bounds__(256, 2)
void gemm_mma_kernel(const int* __restrict__ labels, const float* __restrict__ tptr) {
    extern __shared__ char dsm_raw[];
    __shared__ int lc[TN];

    const int tid  = threadIdx.x;
    const int wid  = tid >> 5;
    const int lane = tid & 31;

    // ---- triangular tile decode: blockIdx.x -> (bi <= bj) ----
    const int k = blockIdx.x;
    int bi = (int)((2.0 * NBLK + 1.0
                    - sqrt((2.0 * NBLK + 1.0) * (2.0 * NBLK + 1.0) - 8.0 * (double)k)) * 0.5);
    while (bi > 0 && bi * NBLK - bi * (bi - 1) / 2 > k) bi--;
    while ((bi + 1) * NBLK - (bi + 1) * bi / 2 <= k) bi++;
    const int bj = bi + (k - (bi * NBLK - bi * (bi - 1) / 2));
    const int row0 = bi * TM;
    const int col0 = bj * TN;
    const bool offdiag = (bi != bj);

    const uint32_t sbase = (smem_u32(dsm_raw) + 127u) & ~127u;

    if (tid < TN) lc[tid] = labels[col0 + tid];

    const char* yP = (const char*)g_Y;

    // per chunk: 2 arrays x 128 rows x 4 units(16B) = 1024 units / 256 thr = 4.
    auto load_chunk = [&](int bufidx, int kc) {
        uint32_t b = sbase + bufidx * BUF_SZ;
        #pragma unroll
        for (int i = 0; i < 4; i++) {
            int idx = tid + i * 256;
            int arr = idx >> 9;              // 0:A 1:B
            int r   = (idx >> 2) & 127;
            int u   = idx & 3;
            uint32_t dof = dof64(r, u) + arr * OFF_B;
            int grow = (arr ? col0 : row0) + r;
            cpa16(b + dof, yP + (size_t)grow * (DDIM * 2) + kc * 64 + u * 16);
        }
    };

    float acc[4][4][4];
    #pragma unroll
    for (int m = 0; m < 4; m++)
        #pragma unroll
        for (int n = 0; n < 4; n++)
            #pragma unroll
            for (int j = 0; j < 4; j++) acc[m][n][j] = 0.0f;

    const int wm = wid & 1, wn = wid >> 1;
    const int sub = lane >> 3, l7 = lane & 7;

    load_chunk(0, 0);
    CPA_COMMIT();
    load_chunk(1, 1);
    CPA_COMMIT();

    const int NCH = DDIM / KCH;  // 8
    int buf = 0;
    #pragma unroll 1
    for (int kc = 0; kc < NCH; kc++) {
        if (kc < NCH - 1) {
            asm volatile("cp.async.wait_group 1;" ::: "memory");
        } else {
            asm volatile("cp.async.wait_group 0;" ::: "memory");
        }
        __syncthreads();

        if (kc + 2 < NCH) {
            load_chunk((buf + 2) % NSTAGE, kc + 2);
            CPA_COMMIT();
        }

        const uint32_t b = sbase + buf * BUF_SZ;
        #pragma unroll
        for (int ks = 0; ks < 2; ks++) {
            uint32_t ah[4][4], bh[2][4];
            #pragma unroll
            for (int ma = 0; ma < 4; ma++) {
                int mr = wm * 64 + ma * 16 + ((sub & 1) << 3) + l7;
                int u  = 2 * ks + (sub >> 1);
                ldsm4(ah[ma], b + OFF_A + dof64(mr, u));
            }
            #pragma unroll
            for (int nb = 0; nb < 2; nb++) {
                int nr = wn * 32 + nb * 16 + ((sub >> 1) << 3) + l7;
                int u  = 2 * ks + (sub & 1);
                ldsm4(bh[nb], b + OFF_B + dof64(nr, u));
            }
            #pragma unroll
            for (int ma = 0; ma < 4; ma++)
                #pragma unroll
                for (int na = 0; na < 4; na++)
                    mma16816(acc[ma][na], ah[ma], &bh[na >> 1][(na & 1) * 2]);
        }
        buf = (buf + 1) % NSTAGE;
    }

    // ---- Epilogue ----
    const float esc = 1.442695041f / (*tptr);
    const float eself = fexp2(esc);          // exact exp(1/t): cos_ii == 1
    const int q = lane & 3, g = lane >> 2;

    int cl_[4][2];
    #pragma unroll
    for (int na = 0; na < 4; na++) {
        cl_[na][0] = lc[wn * 32 + na * 8 + q * 2];
        cl_[na][1] = lc[wn * 32 + na * 8 + q * 2 + 1];
    }

    float ct[4][2], cp[4][2];   // column-side accumulators (off-diag only)
    #pragma unroll
    for (int na = 0; na < 4; na++) { ct[na][0] = ct[na][1] = cp[na][0] = cp[na][1] = 0.f; }

    #pragma unroll
    for (int ma = 0; ma < 4; ma++) {
        int rA = row0 + wm * 64 + ma * 16 + g;
        int rB = rA + 8;
        int lA = __ldg(&labels[rA]), lB = __ldg(&labels[rB]);
        float tsA = 0.f, psA = 0.f, tsB = 0.f, psB = 0.f;
        #pragma unroll
        for (int na = 0; na < 4; na++) {
            float e0 = fexp2(acc[ma][na][0] * esc);
            float e1 = fexp2(acc[ma][na][1] * esc);
            float e2 = fexp2(acc[ma][na][2] * esc);
            float e3 = fexp2(acc[ma][na][3] * esc);
            if (!offdiag) {                  // patch exact self-pairs
                int c0i = col0 + wn * 32 + na * 8 + q * 2;
                if (c0i     == rA) e0 = eself;
                if (c0i + 1 == rA) e1 = eself;
                if (c0i     == rB) e2 = eself;
                if (c0i + 1 == rB) e3 = eself;
            }
            bool m0 = (lA == cl_[na][0]), m1 = (lA == cl_[na][1]);
            bool m2 = (lB == cl_[na][0]), m3 = (lB == cl_[na][1]);
            tsA += e0 + e1;
            tsB += e2 + e3;
            psA += (m0 ? e0 : 1.0f) + (m1 ? e1 : 1.0f);
            psB += (m2 ? e2 : 1.0f) + (m3 ? e3 : 1.0f);
            if (offdiag) {
                ct[na][0] += e0 + e2;
                ct[na][1] += e1 + e3;
                cp[na][0] += (m0 ? e0 : 1.0f) + (m2 ? e2 : 1.0f);
                cp[na][1] += (m1 ? e1 : 1.0f) + (m3 ? e3 : 1.0f);
            }
        }
        #pragma unroll
        for (int o = 1; o <= 2; o <<= 1) {
            tsA += __shfl_xor_sync(0xffffffffu, tsA, o);
            psA += __shfl_xor_sync(0xffffffffu, psA, o);
            tsB += __shfl_xor_sync(0xffffffffu, tsB, o);
            psB += __shfl_xor_sync(0xffffffffu, psB, o);
        }
        if (q == 0) {
            atomicAdd(&g_tot[rA], tsA);
            atomicAdd(&g_pos[rA], psA);
            atomicAdd(&g_tot[rB], tsB);
            atomicAdd(&g_pos[rB], psB);
        }
    }

    if (offdiag) {
        #pragma unroll
        for (int na = 0; na < 4; na++)
            #pragma unroll
            for (int bb = 0; bb < 2; bb++) {
                float t = ct[na][bb], p = cp[na][bb];
                #pragma unroll
                for (int o = 4; o <= 16; o <<= 1) {
                    t += __shfl_xor_sync(0xffffffffu, t, o);
                    p += __shfl_xor_sync(0xffffffffu, p, o);
                }
                if (g == 0) {
                    int col = col0 + wn * 32 + na * 8 + q * 2 + bb;
                    atomicAdd(&g_tot[col], t);
                    atomicAdd(&g_pos[col], p);
                }
            }
    }
}

// ---------------------------------------------------------------------------
// Kernel 3a: per-block partial loss (32 blocks x 256 threads = 8192 rows).
// ---------------------------------------------------------------------------
__global__ void loss_partial_kernel() {
    __shared__ double sd[256];
    int r = blockIdx.x * 256 + threadIdx.x;
    float p  = g_pos[r];
    float ng = g_tot[r] + (float)NROWS - p;
    sd[threadIdx.x] = (double)(logf(ng) - logf(p));
    __syncthreads();
    #pragma unroll
    for (int o = 128; o > 0; o >>= 1) {
        if (threadIdx.x < o) sd[threadIdx.x] += sd[threadIdx.x + o];
        __syncthreads();
    }
    if (threadIdx.x == 0) g_partial[blockIdx.x] = sd[0];
}

// Kernel 3b: final reduce.
__global__ void loss_final_kernel(float* __restrict__ out) {
    double a = (threadIdx.x < 32) ? g_partial[threadIdx.x] : 0.0;
    #pragma unroll
    for (int o = 16; o > 0; o >>= 1) a += __shfl_xor_sync(0xffffffffu, a, o);
    if (threadIdx.x == 0) out[0] = (float)(a / (double)NROWS);
}

// ---------------------------------------------------------------------------
extern "C" void kernel_launch(void* const* d_in, const int* in_sizes, int n_in,
                              void* d_out, int out_size) {
    const float* X   = (const float*)d_in[0];
    const int*   lab = (const int*)d_in[1];
    const float* t   = (const float*)d_in[2];
    float*       out = (float*)d_out;

    cudaFuncSetAttribute(gemm_mma_kernel, cudaFuncAttributeMaxDynamicSharedMemorySize,
                         DSMEM_TOTAL);

    norm_kernel<<<NROWS / 8, 256>>>(X);
    gemm_mma_kernel<<<NTILES, 256, DSMEM_TOTAL>>>(lab, t);
    loss_partial_kernel<<<32, 256>>>();
    loss_final_kernel<<<1, 32>>>(out);
}